// round 8
// baseline (speedup 1.0000x reference)
#include <cuda_runtime.h>
#include <math.h>
#include <stdint.h>

// ---------------- problem constants ----------------
#define BB 8
#define NN 1024
#define CC 512
#define FF 2048
#define M_TOK (BB*NN)          // 8192
#define HEADS 64
#define SCALE 0.125f           // 64^-0.5

// ---------------- scratch (static device, no allocs) ----------------
__device__ float g_xn[M_TOK*CC];            // ln1 output (exact fp32)
__device__ float g_xnr[M_TOK*CC];           // ln1 output rounded to tf32
__device__ float g_qkv[M_TOK*3*CC];         // qkv
__device__ float g_part[64*CC];             // xn partial sums [b][p][c]
__device__ float g_w[2*HEADS*CC];           // wrow then wcol
__device__ float g_scores[2*HEADS*NN];      // row scores then col scores
__device__ float g_mask[2*HEADS*NN];        // row masks then col masks
__device__ float g_attn[M_TOK*CC];          // attention output (tf32-rounded)
__device__ float g_conv[M_TOK*CC];          // conv branch
__device__ float g_xr[M_TOK*CC];            // x_attn + x_conv
__device__ float g_h[M_TOK*CC];             // ln2 output (tf32-rounded)
__device__ float g_ff[M_TOK*FF];            // ff1 output (tf32-rounded)
__device__ float g_wr[3145728];             // rounded weights: qkv|out|ff1|ff2
#define WR_QW 0
#define WR_OW 786432
#define WR_F1 1048576
#define WR_F2 2097152

// ---------------- helpers ----------------
__device__ __forceinline__ uint32_t f2tf(float x) {
    uint32_t u;
    asm("cvt.rna.tf32.f32 %0, %1;" : "=r"(u) : "f"(x));
    return u;
}
__device__ __forceinline__ float rnd_tf32(float x) { return __uint_as_float(f2tf(x)); }
__device__ __forceinline__ void mma8(float* c, const uint32_t* a, const uint32_t* b) {
    asm volatile("mma.sync.aligned.m16n8k8.row.col.f32.tf32.tf32.f32 "
                 "{%0,%1,%2,%3},{%4,%5,%6,%7},{%8,%9},{%0,%1,%2,%3};\n"
                 : "+f"(c[0]), "+f"(c[1]), "+f"(c[2]), "+f"(c[3])
                 : "r"(a[0]), "r"(a[1]), "r"(a[2]), "r"(a[3]), "r"(b[0]), "r"(b[1]));
}
__device__ __forceinline__ uint32_t smem_u32(const void* p) {
    uint32_t a;
    asm("{ .reg .u64 t; cvta.to.shared.u64 t, %1; cvt.u32.u64 %0, t; }" : "=r"(a) : "l"(p));
    return a;
}
#define CP16(dst, src) \
    asm volatile("cp.async.ca.shared.global [%0], [%1], 16;" :: "r"(dst), "l"(src) : "memory")
#define CP_COMMIT() asm volatile("cp.async.commit_group;" ::: "memory")

// ---------------- rna-round a buffer to tf32 values ----------------
__global__ void round_tf32(const float4* __restrict__ in, float4* __restrict__ out, int n4) {
    int i = blockIdx.x * 256 + threadIdx.x;
    if (i < n4) {
        float4 v = in[i];
        v.x = rnd_tf32(v.x); v.y = rnd_tf32(v.y);
        v.z = rnd_tf32(v.z); v.w = rnd_tf32(v.w);
        out[i] = v;
    }
}

// ---------------- layernorm ----------------
// MODE 0: y exact; MODE 1: y rounded to tf32; MODE 2: y exact + y2 rounded
template<int MODE>
__global__ void ln_kernel(const float* __restrict__ x, const float* __restrict__ w,
                          const float* __restrict__ b, float* __restrict__ y,
                          float* __restrict__ y2) {
    int row = blockIdx.x;
    int tid = threadIdx.x;
    const float* xr = x + (size_t)row*CC;
    float v0 = xr[tid], v1 = xr[tid+256];
    __shared__ float red[256];
    red[tid] = v0 + v1; __syncthreads();
    for (int s = 128; s > 0; s >>= 1) { if (tid < s) red[tid] += red[tid+s]; __syncthreads(); }
    float mu = red[0] * (1.0f/CC);
    __syncthreads();
    float d0 = v0 - mu, d1 = v1 - mu;
    red[tid] = d0*d0 + d1*d1; __syncthreads();
    for (int s = 128; s > 0; s >>= 1) { if (tid < s) red[tid] += red[tid+s]; __syncthreads(); }
    float rs = rsqrtf(red[0] * (1.0f/CC) + 1e-6f);
    float o0 = d0*rs*w[tid]     + b[tid];
    float o1 = d1*rs*w[tid+256] + b[tid+256];
    float* yr = y + (size_t)row*CC;
    if (MODE == 1) { yr[tid] = rnd_tf32(o0); yr[tid+256] = rnd_tf32(o1); }
    else           { yr[tid] = o0;           yr[tid+256] = o1; }
    if (MODE == 2) {
        float* y2r = y2 + (size_t)row*CC;
        y2r[tid]     = rnd_tf32(o0);
        y2r[tid+256] = rnd_tf32(o1);
    }
}

// ---------------- xn partial sums for per-batch mean ----------------
__global__ void xn_part(const float* __restrict__ xn, float* __restrict__ part) {
    int b = blockIdx.x, p = blockIdx.y;
    int c = threadIdx.x;
    const float* base = xn + ((size_t)b*NN + p*128)*CC + c;
    float s = 0.f;
    #pragma unroll 8
    for (int r = 0; r < 128; r++) s += base[(size_t)r*CC];
    part[(b*8+p)*CC + c] = s;
}

// ---------------- exact-fp32 mask projection vectors ----------------
__global__ void wvec(const float* __restrict__ part, const float* __restrict__ qkv_w,
                     float* __restrict__ w) {
    int bh = blockIdx.x, b = bh >> 3, h = bh & 7;
    int t = threadIdx.x;
    __shared__ float xb[512];
    __shared__ float kb[64], qb[64];
    float s = 0.f;
    #pragma unroll
    for (int p = 0; p < 8; p++) s += part[(b*8+p)*CC + t];
    xb[t] = s * (1.0f/NN);
    __syncthreads();
    if (t < 64) {
        float sq = 0.f, sk = 0.f;
        const float* wq = qkv_w + (size_t)(h*64 + t)*CC;
        const float* wk = qkv_w + (size_t)(CC + h*64 + t)*CC;
        for (int c = 0; c < CC; c++) { sq += wq[c]*xb[c]; sk += wk[c]*xb[c]; }
        qb[t] = sq; kb[t] = sk;
    }
    __syncthreads();
    float wr = 0.f, wc = 0.f;
    #pragma unroll 8
    for (int d = 0; d < 64; d++) {
        wr += qkv_w[(size_t)(h*64+d)*CC + t]    * kb[d];
        wc += qkv_w[(size_t)(CC+h*64+d)*CC + t] * qb[d];
    }
    w[bh*CC + t]            = wr;
    w[HEADS*CC + bh*CC + t] = wc;
}

// ---------------- row/col scores, all 8 heads per batch in one pass ------------
// identical per-score FMA order and reduction as before (mask bit-stability)
__global__ void head_scores3(const float* __restrict__ xn, const float* __restrict__ w,
                             float* __restrict__ scores) {
    int b = blockIdx.x;            // 8 batches
    int tok0 = blockIdx.y * 8;     // 128 token groups
    __shared__ float wrs[8][512];
    __shared__ float wcs[8][512];
    int tid = threadIdx.x;
    for (int idx = tid; idx < 4096; idx += 256) {
        int h = idx >> 9, c = idx & 511;
        wrs[h][c] = w[(b*8 + h)*CC + c];
        wcs[h][c] = w[HEADS*CC + (b*8 + h)*CC + c];
    }
    __syncthreads();
    int wp = tid >> 5, lane = tid & 31;
    int i = tok0 + wp;
    const float* xr = xn + (size_t)(b*NN + i)*CC;
    float xv[16];
    #pragma unroll
    for (int q = 0; q < 16; q++) xv[q] = xr[lane + q*32];
    #pragma unroll
    for (int h = 0; h < 8; h++) {
        float sr = 0.f, sc = 0.f;
        #pragma unroll
        for (int q = 0; q < 16; q++) {
            int c = lane + q*32;
            sr += xv[q]*wrs[h][c];
            sc += xv[q]*wcs[h][c];
        }
        #pragma unroll
        for (int o = 16; o > 0; o >>= 1) {
            sr += __shfl_down_sync(~0u, sr, o);
            sc += __shfl_down_sync(~0u, sc, o);
        }
        if (lane == 0) {
            scores[(b*8+h)*NN + i]            = sr * SCALE;
            scores[HEADS*NN + (b*8+h)*NN + i] = sc * SCALE;
        }
    }
}

// ---------------- top-k threshold + mask ----------------
__global__ void topk_mask(const float* __restrict__ scores, float* __restrict__ mask) {
    __shared__ float s[1024];
    int blk = blockIdx.x, tid = threadIdx.x;
    float v = scores[(size_t)blk*1024 + tid];
    s[tid] = v; __syncthreads();
    for (int k = 2; k <= 1024; k <<= 1) {
        for (int j = k >> 1; j > 0; j >>= 1) {
            int ixj = tid ^ j;
            if (ixj > tid) {
                bool up = ((tid & k) == 0);
                float a = s[tid], bb = s[ixj];
                if ((a > bb) == up) { s[tid] = bb; s[ixj] = a; }
            }
            __syncthreads();
        }
    }
    float thr = s[512];
    mask[(size_t)blk*1024 + tid] = (v >= thr) ? 1.0f : 0.0f;
}

// ---------------- depthwise 3x3 conv branch ----------------
__global__ void dwconv(const float* __restrict__ x, const float* __restrict__ w,
                       const float* __restrict__ b, float* __restrict__ out) {
    int bn = blockIdx.x;
    int bt = bn >> 10, n = bn & 1023;
    int hh = n >> 5, ww = n & 31;
    int c = threadIdx.x;
    float acc = b[c];
    #pragma unroll
    for (int dh = 0; dh < 3; dh++) {
        int y = hh + dh - 1;
        if (y < 0 || y >= 32) continue;
        #pragma unroll
        for (int dw = 0; dw < 3; dw++) {
            int xw = ww + dw - 1;
            if (xw < 0 || xw >= 32) continue;
            acc += x[(size_t)(bt*NN + y*32 + xw)*CC + c] * w[c*9 + dh*3 + dw];
        }
    }
    out[(size_t)bn*CC + c] = acc;
}

// ---------------- fused flash attention (tf32 mma, online softmax) ----------------
// rna rounding at all smem stores; epilogue rounds output (feeds out-proj GEMM)
#define QK_PAD 68
#define P_PAD 132
__global__ void __launch_bounds__(256, 1)
flash_attn(const float* __restrict__ qkv, const float* __restrict__ mask,
           float* __restrict__ out) {
    extern __shared__ uint32_t sm[];
    uint32_t (*Qs)[QK_PAD] = (uint32_t(*)[QK_PAD])sm;
    uint32_t (*Ks)[QK_PAD] = (uint32_t(*)[QK_PAD])(sm + 128*QK_PAD);
    uint32_t (*Vs)[QK_PAD] = (uint32_t(*)[QK_PAD])(sm + 2*128*QK_PAD);
    uint32_t (*Ps)[P_PAD]  = (uint32_t(*)[P_PAD]) (sm + 3*128*QK_PAD);

    int bh = blockIdx.y, b = bh >> 3, h = bh & 7;
    int mb = blockIdx.x * 128;
    int tid = threadIdx.x, warp = tid >> 5, lane = tid & 31;
    int g = lane >> 2, tg = lane & 3;
    int wm = warp * 16;

    const float* qbase = qkv + (size_t)b*NN*(3*CC) + h*64;
    const float* rmask = mask + bh*NN;
    const float* cmask = mask + HEADS*NN + bh*NN;

    #pragma unroll
    for (int u = 0; u < 8; u++) {
        int f = tid + u*256;
        int r = f >> 4, c4 = (f & 15) * 4;
        float4 v = *(const float4*)(qbase + (size_t)(mb + r)*(3*CC) + c4);
        float s = SCALE * rmask[mb + r];
        Qs[r][c4+0] = f2tf(v.x*s); Qs[r][c4+1] = f2tf(v.y*s);
        Qs[r][c4+2] = f2tf(v.z*s); Qs[r][c4+3] = f2tf(v.w*s);
    }
    __syncthreads();

    uint32_t qf[8][4];
    #pragma unroll
    for (int ks = 0; ks < 8; ks++) {
        qf[ks][0] = Qs[wm+g  ][ks*8+tg];
        qf[ks][1] = Qs[wm+g+8][ks*8+tg];
        qf[ks][2] = Qs[wm+g  ][ks*8+tg+4];
        qf[ks][3] = Qs[wm+g+8][ks*8+tg+4];
    }

    float o[8][4];
    #pragma unroll
    for (int j = 0; j < 8; j++)
        #pragma unroll
        for (int q = 0; q < 4; q++) o[j][q] = 0.f;
    float m0 = -1e30f, m1 = -1e30f, l0 = 0.f, l1 = 0.f;

    for (int kt = 0; kt < 8; kt++) {
        int kv0 = kt * 128;
        __syncthreads();
        #pragma unroll
        for (int u = 0; u < 8; u++) {
            int f = tid + u*256;
            int r = f >> 4, c4 = (f & 15) * 4;
            const float* kp = qbase + CC   + (size_t)(kv0 + r)*(3*CC) + c4;
            const float* vp = qbase + 2*CC + (size_t)(kv0 + r)*(3*CC) + c4;
            float cm = cmask[kv0 + r];
            float4 kv = *(const float4*)kp;
            float4 vv = *(const float4*)vp;
            Ks[r][c4+0] = f2tf(kv.x*cm); Ks[r][c4+1] = f2tf(kv.y*cm);
            Ks[r][c4+2] = f2tf(kv.z*cm); Ks[r][c4+3] = f2tf(kv.w*cm);
            Vs[r][c4+0] = f2tf(vv.x);    Vs[r][c4+1] = f2tf(vv.y);
            Vs[r][c4+2] = f2tf(vv.z);    Vs[r][c4+3] = f2tf(vv.w);
        }
        __syncthreads();

        float s[16][4];
        #pragma unroll
        for (int j = 0; j < 16; j++)
            #pragma unroll
            for (int q = 0; q < 4; q++) s[j][q] = 0.f;
        #pragma unroll
        for (int j = 0; j < 16; j++) {
            #pragma unroll
            for (int ks = 0; ks < 8; ks++) {
                uint32_t bf[2];
                bf[0] = Ks[j*8+g][ks*8+tg];
                bf[1] = Ks[j*8+g][ks*8+tg+4];
                mma8(s[j], qf[ks], bf);
            }
        }

        float tm0 = -1e30f, tm1 = -1e30f;
        #pragma unroll
        for (int j = 0; j < 16; j++) {
            tm0 = fmaxf(tm0, fmaxf(s[j][0], s[j][1]));
            tm1 = fmaxf(tm1, fmaxf(s[j][2], s[j][3]));
        }
        tm0 = fmaxf(tm0, __shfl_xor_sync(~0u, tm0, 1));
        tm0 = fmaxf(tm0, __shfl_xor_sync(~0u, tm0, 2));
        tm1 = fmaxf(tm1, __shfl_xor_sync(~0u, tm1, 1));
        tm1 = fmaxf(tm1, __shfl_xor_sync(~0u, tm1, 2));
        float mn0 = fmaxf(m0, tm0), mn1 = fmaxf(m1, tm1);
        float a0 = __expf(m0 - mn0), a1 = __expf(m1 - mn1);
        float rs0 = 0.f, rs1 = 0.f;
        #pragma unroll
        for (int j = 0; j < 16; j++) {
            float p00 = __expf(s[j][0] - mn0);
            float p01 = __expf(s[j][1] - mn0);
            float p10 = __expf(s[j][2] - mn1);
            float p11 = __expf(s[j][3] - mn1);
            rs0 += p00 + p01; rs1 += p10 + p11;
            Ps[wm+g  ][j*8+2*tg]   = f2tf(p00);
            Ps[wm+g  ][j*8+2*tg+1] = f2tf(p01);
            Ps[wm+g+8][j*8+2*tg]   = f2tf(p10);
            Ps[wm+g+8][j*8+2*tg+1] = f2tf(p11);
        }
        rs0 += __shfl_xor_sync(~0u, rs0, 1); rs0 += __shfl_xor_sync(~0u, rs0, 2);
        rs1 += __shfl_xor_sync(~0u, rs1, 1); rs1 += __shfl_xor_sync(~0u, rs1, 2);
        l0 = l0*a0 + rs0; l1 = l1*a1 + rs1;
        m0 = mn0; m1 = mn1;
        #pragma unroll
        for (int j = 0; j < 8; j++) {
            o[j][0] *= a0; o[j][1] *= a0; o[j][2] *= a1; o[j][3] *= a1;
        }
        __syncwarp();

        #pragma unroll
        for (int ks = 0; ks < 16; ks++) {
            uint32_t af[4];
            af[0] = Ps[wm+g  ][ks*8+tg];
            af[1] = Ps[wm+g+8][ks*8+tg];
            af[2] = Ps[wm+g  ][ks*8+tg+4];
            af[3] = Ps[wm+g+8][ks*8+tg+4];
            #pragma unroll
            for (int jd = 0; jd < 8; jd++) {
                uint32_t bf[2];
                bf[0] = Vs[ks*8+tg  ][jd*8+g];
                bf[1] = Vs[ks*8+tg+4][jd*8+g];
                mma8(o[jd], af, bf);
            }
        }
    }

    float il0 = 1.0f / l0, il1 = 1.0f / l1;
    int r0 = b*NN + mb + wm + g, r1 = r0 + 8;
    #pragma unroll
    for (int jd = 0; jd < 8; jd++) {
        int c0 = h*64 + jd*8 + 2*tg;
        out[(size_t)r0*CC + c0]     = rnd_tf32(o[jd][0]*il0);
        out[(size_t)r0*CC + c0 + 1] = rnd_tf32(o[jd][1]*il0);
        out[(size_t)r1*CC + c0]     = rnd_tf32(o[jd][2]*il1);
        out[(size_t)r1*CC + c0 + 1] = rnd_tf32(o[jd][3]*il1);
    }
}

// ---------------- tf32 tensor-core GEMM (NT), cp.async 3-stage pipeline ----------
// operands are pre-rounded tf32 values in gmem -> HW truncation is lossless.
// EP: 0 plain; 1 +bias[n](+addm); 2 gelu(v+bias[n]) rounded to tf32.
#define TG_STG 3
#define TG_STRIDE 20
#define TG_STAGE_F (128 * TG_STRIDE)
#define TG_SMEM (TG_STG * 2 * TG_STAGE_F * 4)     // 61440 bytes
template<int EP>
__global__ __launch_bounds__(256)
void tgemm(const float* __restrict__ A, int lda,
           const float* __restrict__ B, int ldb,
           float* __restrict__ C, int ldc, int K,
           const float* __restrict__ bias, const float* __restrict__ addm)
{
    constexpr int BM = 128, BN = 128, BK = 16;
    extern __shared__ float tsm[];
    auto As = [&](int s) -> float* { return tsm + s * 2 * TG_STAGE_F; };
    auto Bs = [&](int s) -> float* { return tsm + s * 2 * TG_STAGE_F + TG_STAGE_F; };

    int tid = threadIdx.x;
    int warp = tid >> 5, lane = tid & 31;
    int wm = (warp & 1) * 64, wn = (warp >> 1) * 32;
    int g = lane >> 2, tg = lane & 3;
    int bm = blockIdx.y * BM, bn = blockIdx.x * BN;

    float acc[4][4][4];
    #pragma unroll
    for (int i = 0; i < 4; i++)
        #pragma unroll
        for (int j = 0; j < 4; j++)
            #pragma unroll
            for (int q = 0; q < 4; q++) acc[i][j][q] = 0.f;

    int lrow = tid >> 2, lk4 = (tid & 3) * 4;
    const float* Ab = A + (size_t)(bm + lrow) * lda + lk4;
    const float* Bb = B + (size_t)(bn + lrow) * ldb + lk4;
    const float* Ab2 = Ab + (size_t)64 * lda;
    const float* Bb2 = Bb + (size_t)64 * ldb;

    auto issue = [&](int kt, int s) {
        CP16(smem_u32(As(s) + lrow*TG_STRIDE + lk4),        Ab  + kt);
        CP16(smem_u32(As(s) + (lrow+64)*TG_STRIDE + lk4),   Ab2 + kt);
        CP16(smem_u32(Bs(s) + lrow*TG_STRIDE + lk4),        Bb  + kt);
        CP16(smem_u32(Bs(s) + (lrow+64)*TG_STRIDE + lk4),   Bb2 + kt);
        CP_COMMIT();
    };

    int nk = K / BK;
    issue(0, 0);
    if (nk > 1) issue(BK, 1);

    for (int c = 0; c < nk; c++) {
        if (c + 1 < nk) asm volatile("cp.async.wait_group 1;" ::: "memory");
        else            asm volatile("cp.async.wait_group 0;" ::: "memory");
        __syncthreads();
        int s = c % TG_STG;
        const float* as = As(s);
        const float* bs = Bs(s);

        #pragma unroll
        for (int ks = 0; ks < 16; ks += 8) {
            uint32_t af[4][4]; uint32_t bf[4][2];
            #pragma unroll
            for (int i = 0; i < 4; i++) {
                int r = wm + 16*i + g;
                af[i][0] = __float_as_uint(as[r*TG_STRIDE     + ks+tg]);
                af[i][1] = __float_as_uint(as[(r+8)*TG_STRIDE + ks+tg]);
                af[i][2] = __float_as_uint(as[r*TG_STRIDE     + ks+tg+4]);
                af[i][3] = __float_as_uint(as[(r+8)*TG_STRIDE + ks+tg+4]);
            }
            #pragma unroll
            for (int j = 0; j < 4; j++) {
                int n = wn + 8*j + g;
                bf[j][0] = __float_as_uint(bs[n*TG_STRIDE + ks+tg]);
                bf[j][1] = __float_as_uint(bs[n*TG_STRIDE + ks+tg+4]);
            }
            #pragma unroll
            for (int i = 0; i < 4; i++)
                #pragma unroll
                for (int j = 0; j < 4; j++)
                    mma8(acc[i][j], af[i], bf[j]);
        }

        if (c + 2 < nk) issue((c + 2) * BK, (c + 2) % TG_STG);
    }

    #pragma unroll
    for (int i = 0; i < 4; i++) {
        int r0 = bm + wm + 16*i + g;
        int r1 = r0 + 8;
        #pragma unroll
        for (int j = 0; j < 4; j++) {
            int c0 = bn + wn + 8*j + tg*2;
            float v00 = acc[i][j][0], v01 = acc[i][j][1];
            float v10 = acc[i][j][2], v11 = acc[i][j][3];
            if (EP == 1 || EP == 2) {
                float b0 = bias[c0], b1 = bias[c0+1];
                v00 += b0; v01 += b1; v10 += b0; v11 += b1;
            }
            if (EP == 1 && addm) {
                v00 += addm[(size_t)r0*ldc + c0]; v01 += addm[(size_t)r0*ldc + c0 + 1];
                v10 += addm[(size_t)r1*ldc + c0]; v11 += addm[(size_t)r1*ldc + c0 + 1];
            }
            if (EP == 2) {
                v00 = rnd_tf32(0.5f*v00*(1.0f + erff(v00*0.70710678118654752f)));
                v01 = rnd_tf32(0.5f*v01*(1.0f + erff(v01*0.70710678118654752f)));
                v10 = rnd_tf32(0.5f*v10*(1.0f + erff(v10*0.70710678118654752f)));
                v11 = rnd_tf32(0.5f*v11*(1.0f + erff(v11*0.70710678118654752f)));
            }
            C[(size_t)r0*ldc + c0]     = v00;
            C[(size_t)r0*ldc + c0 + 1] = v01;
            C[(size_t)r1*ldc + c0]     = v10;
            C[(size_t)r1*ldc + c0 + 1] = v11;
        }
    }
}

// ---------------- launch ----------------
extern "C" void kernel_launch(void* const* d_in, const int* in_sizes, int n_in,
                              void* d_out, int out_size) {
    const float* x      = (const float*)d_in[0];
    const float* ln1_w  = (const float*)d_in[1];
    const float* ln1_b  = (const float*)d_in[2];
    const float* qkv_w  = (const float*)d_in[3];
    const float* out_w  = (const float*)d_in[4];
    const float* out_b  = (const float*)d_in[5];
    const float* conv_w = (const float*)d_in[6];
    const float* conv_b = (const float*)d_in[7];
    const float* ln2_w  = (const float*)d_in[8];
    const float* ln2_b  = (const float*)d_in[9];
    const float* ff1_w  = (const float*)d_in[10];
    const float* ff1_b  = (const float*)d_in[11];
    const float* ff2_w  = (const float*)d_in[12];
    const float* ff2_b  = (const float*)d_in[13];
    float* out = (float*)d_out;

    float *xn, *xnr, *qkv, *part, *wv, *scores, *mask, *attn, *conv, *xr, *hbuf, *ff, *wr;
    cudaGetSymbolAddress((void**)&xn,     g_xn);
    cudaGetSymbolAddress((void**)&xnr,    g_xnr);
    cudaGetSymbolAddress((void**)&qkv,    g_qkv);
    cudaGetSymbolAddress((void**)&part,   g_part);
    cudaGetSymbolAddress((void**)&wv,     g_w);
    cudaGetSymbolAddress((void**)&scores, g_scores);
    cudaGetSymbolAddress((void**)&mask,   g_mask);
    cudaGetSymbolAddress((void**)&attn,   g_attn);
    cudaGetSymbolAddress((void**)&conv,   g_conv);
    cudaGetSymbolAddress((void**)&xr,     g_xr);
    cudaGetSymbolAddress((void**)&hbuf,   g_h);
    cudaGetSymbolAddress((void**)&ff,     g_ff);
    cudaGetSymbolAddress((void**)&wr,     g_wr);

    // idempotent every call (capture-safe, no static guards)
    const int FA_SMEM = (3*128*QK_PAD + 128*P_PAD) * 4;   // 172032 B
    cudaFuncSetAttribute(flash_attn, cudaFuncAttributeMaxDynamicSharedMemorySize, FA_SMEM);
    cudaFuncSetAttribute(tgemm<0>, cudaFuncAttributeMaxDynamicSharedMemorySize, TG_SMEM);
    cudaFuncSetAttribute(tgemm<1>, cudaFuncAttributeMaxDynamicSharedMemorySize, TG_SMEM);
    cudaFuncSetAttribute(tgemm<2>, cudaFuncAttributeMaxDynamicSharedMemorySize, TG_SMEM);

    // 0. round weights to tf32 (rna) once per invocation
    round_tf32<<<768,  256>>>((const float4*)qkv_w, (float4*)(wr + WR_QW), 786432/4);
    round_tf32<<<256,  256>>>((const float4*)out_w, (float4*)(wr + WR_OW), 262144/4);
    round_tf32<<<1024, 256>>>((const float4*)ff1_w, (float4*)(wr + WR_F1), 1048576/4);
    round_tf32<<<1024, 256>>>((const float4*)ff2_w, (float4*)(wr + WR_F2), 1048576/4);

    // 1. LN1: exact xn + rounded xnr
    ln_kernel<2><<<M_TOK, 256>>>(x, ln1_w, ln1_b, xn, xnr);

    // 2. exact fp32 mask path (uses exact xn and exact qkv_w)
    xn_part<<<dim3(8, 8), 512>>>(xn, part);
    wvec<<<HEADS, 512>>>(part, qkv_w, wv);
    head_scores3<<<dim3(8, 128), 256>>>(xn, wv, scores);
    topk_mask<<<2*HEADS, 1024>>>(scores, mask);

    // 3. QKV = xnr @ qkv_w_r^T (tf32, cp.async pipeline, lossless truncation)
    tgemm<0><<<dim3(12, 64), 256, TG_SMEM>>>(xnr, CC, wr + WR_QW, CC, qkv, 3*CC, CC, nullptr, nullptr);

    // 4. fused attention (rna inside; output rounded)
    flash_attn<<<dim3(8, HEADS), 256, FA_SMEM>>>(qkv, mask, attn);

    // 5. conv branch
    dwconv<<<M_TOK, CC>>>(x, conv_w, conv_b, conv);

    // 6. out-proj + bias + conv -> xr (unrounded; feeds LN2 + residual)
    tgemm<1><<<dim3(4, 64), 256, TG_SMEM>>>(attn, CC, wr + WR_OW, CC, xr, CC, CC, out_b, conv);

    // 7. LN2 -> rounded hbuf
    ln_kernel<1><<<M_TOK, 256>>>(xr, ln2_w, ln2_b, hbuf, nullptr);

    // 8. FF1 + gelu (rounded output)
    tgemm<2><<<dim3(16, 64), 256, TG_SMEM>>>(hbuf, CC, wr + WR_F1, CC, ff, FF, CC, ff1_b, nullptr);

    // 9. FF2 + bias + residual -> out (unrounded final)
    tgemm<1><<<dim3(4, 64), 256, TG_SMEM>>>(ff, FF, wr + WR_F2, FF, out, CC, FF, ff2_b, xr);
}

// round 9
// speedup vs baseline: 1.0209x; 1.0209x over previous
#include <cuda_runtime.h>
#include <math.h>
#include <stdint.h>

// ---------------- problem constants ----------------
#define BB 8
#define NN 1024
#define CC 512
#define FF 2048
#define M_TOK (BB*NN)          // 8192
#define HEADS 64
#define SCALE 0.125f           // 64^-0.5

// ---------------- scratch (static device, no allocs) ----------------
__device__ float g_xn[M_TOK*CC];            // ln1 output (exact fp32)
__device__ float g_xnr[M_TOK*CC];           // ln1 output rounded to tf32
__device__ float g_qkv[M_TOK*3*CC];         // qkv
__device__ float g_part[64*CC];             // xn partial sums [b][p][c]
__device__ float g_w[2*HEADS*CC];           // wrow then wcol
__device__ float g_scores[2*HEADS*NN];      // row scores then col scores
__device__ float g_mask[2*HEADS*NN];        // row masks then col masks
__device__ float g_attn[M_TOK*CC];          // attention output (tf32-rounded)
__device__ float g_conv[M_TOK*CC];          // conv branch
__device__ float g_xr[M_TOK*CC];            // x_attn + x_conv
__device__ float g_h[M_TOK*CC];             // ln2 output (tf32-rounded)
__device__ float g_ff[M_TOK*FF];            // ff1 output (tf32-rounded)
__device__ float g_wr[3145728];             // rounded weights: qkv|out|ff1|ff2
#define WR_QW 0
#define WR_OW 786432
#define WR_F1 1048576
#define WR_F2 2097152

// ---------------- helpers ----------------
__device__ __forceinline__ uint32_t f2tf(float x) {
    uint32_t u;
    asm("cvt.rna.tf32.f32 %0, %1;" : "=r"(u) : "f"(x));
    return u;
}
__device__ __forceinline__ float rnd_tf32(float x) { return __uint_as_float(f2tf(x)); }
__device__ __forceinline__ void mma8(float* c, const uint32_t* a, const uint32_t* b) {
    asm volatile("mma.sync.aligned.m16n8k8.row.col.f32.tf32.tf32.f32 "
                 "{%0,%1,%2,%3},{%4,%5,%6,%7},{%8,%9},{%0,%1,%2,%3};\n"
                 : "+f"(c[0]), "+f"(c[1]), "+f"(c[2]), "+f"(c[3])
                 : "r"(a[0]), "r"(a[1]), "r"(a[2]), "r"(a[3]), "r"(b[0]), "r"(b[1]));
}
__device__ __forceinline__ uint32_t smem_u32(const void* p) {
    uint32_t a;
    asm("{ .reg .u64 t; cvta.to.shared.u64 t, %1; cvt.u32.u64 %0, t; }" : "=r"(a) : "l"(p));
    return a;
}
#define CP16(dst, src) \
    asm volatile("cp.async.ca.shared.global [%0], [%1], 16;" :: "r"(dst), "l"(src) : "memory")
#define CP_COMMIT() asm volatile("cp.async.commit_group;" ::: "memory")

// ---------------- rna-round a buffer to tf32 values ----------------
__global__ void round_tf32(const float4* __restrict__ in, float4* __restrict__ out, int n4) {
    int i = blockIdx.x * 256 + threadIdx.x;
    if (i < n4) {
        float4 v = in[i];
        v.x = rnd_tf32(v.x); v.y = rnd_tf32(v.y);
        v.z = rnd_tf32(v.z); v.w = rnd_tf32(v.w);
        out[i] = v;
    }
}

// ---------------- layernorm (warp-shuffle reductions) ----------------
// MODE 1: y rounded to tf32; MODE 2: y exact + y2 rounded
template<int MODE>
__global__ void ln_kernel(const float* __restrict__ x, const float* __restrict__ w,
                          const float* __restrict__ b, float* __restrict__ y,
                          float* __restrict__ y2) {
    int row = blockIdx.x;
    int tid = threadIdx.x, lane = tid & 31, wp = tid >> 5;
    const float* xr = x + (size_t)row*CC;
    float v0 = xr[tid], v1 = xr[tid+256];
    __shared__ float red[8];
    float s = v0 + v1;
    #pragma unroll
    for (int o = 16; o; o >>= 1) s += __shfl_xor_sync(~0u, s, o);
    if (lane == 0) red[wp] = s;
    __syncthreads();
    float tot = red[0]+red[1]+red[2]+red[3]+red[4]+red[5]+red[6]+red[7];
    float mu = tot * (1.0f/CC);
    float d0 = v0 - mu, d1 = v1 - mu;
    float q = d0*d0 + d1*d1;
    __syncthreads();
    #pragma unroll
    for (int o = 16; o; o >>= 1) q += __shfl_xor_sync(~0u, q, o);
    if (lane == 0) red[wp] = q;
    __syncthreads();
    float vtot = red[0]+red[1]+red[2]+red[3]+red[4]+red[5]+red[6]+red[7];
    float rs = rsqrtf(vtot * (1.0f/CC) + 1e-6f);
    float o0 = d0*rs*w[tid]     + b[tid];
    float o1 = d1*rs*w[tid+256] + b[tid+256];
    float* yr = y + (size_t)row*CC;
    if (MODE == 1) { yr[tid] = rnd_tf32(o0); yr[tid+256] = rnd_tf32(o1); }
    else           { yr[tid] = o0;           yr[tid+256] = o1; }
    if (MODE == 2) {
        float* y2r = y2 + (size_t)row*CC;
        y2r[tid]     = rnd_tf32(o0);
        y2r[tid+256] = rnd_tf32(o1);
    }
}

// ---------------- xn partial sums for per-batch mean ----------------
__global__ void xn_part(const float* __restrict__ xn, float* __restrict__ part) {
    int b = blockIdx.x, p = blockIdx.y;
    int c = threadIdx.x;
    const float* base = xn + ((size_t)b*NN + p*128)*CC + c;
    float s = 0.f;
    #pragma unroll 8
    for (int r = 0; r < 128; r++) s += base[(size_t)r*CC];
    part[(b*8+p)*CC + c] = s;
}

// ---------------- exact-fp32 mask projection vectors ----------------
__global__ void wvec(const float* __restrict__ part, const float* __restrict__ qkv_w,
                     float* __restrict__ w) {
    int bh = blockIdx.x, b = bh >> 3, h = bh & 7;
    int t = threadIdx.x;
    __shared__ float xb[512];
    __shared__ float kb[64], qb[64];
    float s = 0.f;
    #pragma unroll
    for (int p = 0; p < 8; p++) s += part[(b*8+p)*CC + t];
    xb[t] = s * (1.0f/NN);
    __syncthreads();
    if (t < 64) {
        float sq = 0.f, sk = 0.f;
        const float* wq = qkv_w + (size_t)(h*64 + t)*CC;
        const float* wk = qkv_w + (size_t)(CC + h*64 + t)*CC;
        for (int c = 0; c < CC; c++) { sq += wq[c]*xb[c]; sk += wk[c]*xb[c]; }
        qb[t] = sq; kb[t] = sk;
    }
    __syncthreads();
    float wr = 0.f, wc = 0.f;
    #pragma unroll 8
    for (int d = 0; d < 64; d++) {
        wr += qkv_w[(size_t)(h*64+d)*CC + t]    * kb[d];
        wc += qkv_w[(size_t)(CC+h*64+d)*CC + t] * qb[d];
    }
    w[bh*CC + t]            = wr;
    w[HEADS*CC + bh*CC + t] = wc;
}

// ---------------- row/col scores, all 8 heads per batch in one pass ------------
__global__ void head_scores3(const float* __restrict__ xn, const float* __restrict__ w,
                             float* __restrict__ scores) {
    int b = blockIdx.x;
    int tok0 = blockIdx.y * 8;
    __shared__ float wrs[8][512];
    __shared__ float wcs[8][512];
    int tid = threadIdx.x;
    for (int idx = tid; idx < 4096; idx += 256) {
        int h = idx >> 9, c = idx & 511;
        wrs[h][c] = w[(b*8 + h)*CC + c];
        wcs[h][c] = w[HEADS*CC + (b*8 + h)*CC + c];
    }
    __syncthreads();
    int wp = tid >> 5, lane = tid & 31;
    int i = tok0 + wp;
    const float* xr = xn + (size_t)(b*NN + i)*CC;
    float xv[16];
    #pragma unroll
    for (int q = 0; q < 16; q++) xv[q] = xr[lane + q*32];
    #pragma unroll
    for (int h = 0; h < 8; h++) {
        float sr = 0.f, sc = 0.f;
        #pragma unroll
        for (int q = 0; q < 16; q++) {
            int c = lane + q*32;
            sr += xv[q]*wrs[h][c];
            sc += xv[q]*wcs[h][c];
        }
        #pragma unroll
        for (int o = 16; o > 0; o >>= 1) {
            sr += __shfl_down_sync(~0u, sr, o);
            sc += __shfl_down_sync(~0u, sc, o);
        }
        if (lane == 0) {
            scores[(b*8+h)*NN + i]            = sr * SCALE;
            scores[HEADS*NN + (b*8+h)*NN + i] = sc * SCALE;
        }
    }
}

// ---------------- top-k threshold + mask ----------------
__global__ void topk_mask(const float* __restrict__ scores, float* __restrict__ mask) {
    __shared__ float s[1024];
    int blk = blockIdx.x, tid = threadIdx.x;
    float v = scores[(size_t)blk*1024 + tid];
    s[tid] = v; __syncthreads();
    for (int k = 2; k <= 1024; k <<= 1) {
        for (int j = k >> 1; j > 0; j >>= 1) {
            int ixj = tid ^ j;
            if (ixj > tid) {
                bool up = ((tid & k) == 0);
                float a = s[tid], bb = s[ixj];
                if ((a > bb) == up) { s[tid] = bb; s[ixj] = a; }
            }
            __syncthreads();
        }
    }
    float thr = s[512];
    mask[(size_t)blk*1024 + tid] = (v >= thr) ? 1.0f : 0.0f;
}

// ---------------- depthwise 3x3 conv branch ----------------
__global__ void dwconv(const float* __restrict__ x, const float* __restrict__ w,
                       const float* __restrict__ b, float* __restrict__ out) {
    int bn = blockIdx.x;
    int bt = bn >> 10, n = bn & 1023;
    int hh = n >> 5, ww = n & 31;
    int c = threadIdx.x;
    float acc = b[c];
    #pragma unroll
    for (int dh = 0; dh < 3; dh++) {
        int y = hh + dh - 1;
        if (y < 0 || y >= 32) continue;
        #pragma unroll
        for (int dw = 0; dw < 3; dw++) {
            int xw = ww + dw - 1;
            if (xw < 0 || xw >= 32) continue;
            acc += x[(size_t)(bt*NN + y*32 + xw)*CC + c] * w[c*9 + dh*3 + dw];
        }
    }
    out[(size_t)bn*CC + c] = acc;
}

// ---------------- fused flash attention (tf32 mma, online softmax) ----------------
#define QK_PAD 68
#define P_PAD 132
__global__ void __launch_bounds__(256, 1)
flash_attn(const float* __restrict__ qkv, const float* __restrict__ mask,
           float* __restrict__ out) {
    extern __shared__ uint32_t sm[];
    uint32_t (*Qs)[QK_PAD] = (uint32_t(*)[QK_PAD])sm;
    uint32_t (*Ks)[QK_PAD] = (uint32_t(*)[QK_PAD])(sm + 128*QK_PAD);
    uint32_t (*Vs)[QK_PAD] = (uint32_t(*)[QK_PAD])(sm + 2*128*QK_PAD);
    uint32_t (*Ps)[P_PAD]  = (uint32_t(*)[P_PAD]) (sm + 3*128*QK_PAD);

    int bh = blockIdx.y, b = bh >> 3, h = bh & 7;
    int mb = blockIdx.x * 128;
    int tid = threadIdx.x, warp = tid >> 5, lane = tid & 31;
    int g = lane >> 2, tg = lane & 3;
    int wm = warp * 16;

    const float* qbase = qkv + (size_t)b*NN*(3*CC) + h*64;
    const float* rmask = mask + bh*NN;
    const float* cmask = mask + HEADS*NN + bh*NN;

    #pragma unroll
    for (int u = 0; u < 8; u++) {
        int f = tid + u*256;
        int r = f >> 4, c4 = (f & 15) * 4;
        float4 v = *(const float4*)(qbase + (size_t)(mb + r)*(3*CC) + c4);
        float s = SCALE * rmask[mb + r];
        Qs[r][c4+0] = f2tf(v.x*s); Qs[r][c4+1] = f2tf(v.y*s);
        Qs[r][c4+2] = f2tf(v.z*s); Qs[r][c4+3] = f2tf(v.w*s);
    }
    __syncthreads();

    uint32_t qf[8][4];
    #pragma unroll
    for (int ks = 0; ks < 8; ks++) {
        qf[ks][0] = Qs[wm+g  ][ks*8+tg];
        qf[ks][1] = Qs[wm+g+8][ks*8+tg];
        qf[ks][2] = Qs[wm+g  ][ks*8+tg+4];
        qf[ks][3] = Qs[wm+g+8][ks*8+tg+4];
    }

    float o[8][4];
    #pragma unroll
    for (int j = 0; j < 8; j++)
        #pragma unroll
        for (int q = 0; q < 4; q++) o[j][q] = 0.f;
    float m0 = -1e30f, m1 = -1e30f, l0 = 0.f, l1 = 0.f;

    for (int kt = 0; kt < 8; kt++) {
        int kv0 = kt * 128;
        __syncthreads();
        #pragma unroll
        for (int u = 0; u < 8; u++) {
            int f = tid + u*256;
            int r = f >> 4, c4 = (f & 15) * 4;
            const float* kp = qbase + CC   + (size_t)(kv0 + r)*(3*CC) + c4;
            const float* vp = qbase + 2*CC + (size_t)(kv0 + r)*(3*CC) + c4;
            float cm = cmask[kv0 + r];
            float4 kv = *(const float4*)kp;
            float4 vv = *(const float4*)vp;
            Ks[r][c4+0] = f2tf(kv.x*cm); Ks[r][c4+1] = f2tf(kv.y*cm);
            Ks[r][c4+2] = f2tf(kv.z*cm); Ks[r][c4+3] = f2tf(kv.w*cm);
            Vs[r][c4+0] = f2tf(vv.x);    Vs[r][c4+1] = f2tf(vv.y);
            Vs[r][c4+2] = f2tf(vv.z);    Vs[r][c4+3] = f2tf(vv.w);
        }
        __syncthreads();

        float s[16][4];
        #pragma unroll
        for (int j = 0; j < 16; j++)
            #pragma unroll
            for (int q = 0; q < 4; q++) s[j][q] = 0.f;
        #pragma unroll
        for (int j = 0; j < 16; j++) {
            #pragma unroll
            for (int ks = 0; ks < 8; ks++) {
                uint32_t bf[2];
                bf[0] = Ks[j*8+g][ks*8+tg];
                bf[1] = Ks[j*8+g][ks*8+tg+4];
                mma8(s[j], qf[ks], bf);
            }
        }

        float tm0 = -1e30f, tm1 = -1e30f;
        #pragma unroll
        for (int j = 0; j < 16; j++) {
            tm0 = fmaxf(tm0, fmaxf(s[j][0], s[j][1]));
            tm1 = fmaxf(tm1, fmaxf(s[j][2], s[j][3]));
        }
        tm0 = fmaxf(tm0, __shfl_xor_sync(~0u, tm0, 1));
        tm0 = fmaxf(tm0, __shfl_xor_sync(~0u, tm0, 2));
        tm1 = fmaxf(tm1, __shfl_xor_sync(~0u, tm1, 1));
        tm1 = fmaxf(tm1, __shfl_xor_sync(~0u, tm1, 2));
        float mn0 = fmaxf(m0, tm0), mn1 = fmaxf(m1, tm1);
        float a0 = __expf(m0 - mn0), a1 = __expf(m1 - mn1);
        float rs0 = 0.f, rs1 = 0.f;
        #pragma unroll
        for (int j = 0; j < 16; j++) {
            float p00 = __expf(s[j][0] - mn0);
            float p01 = __expf(s[j][1] - mn0);
            float p10 = __expf(s[j][2] - mn1);
            float p11 = __expf(s[j][3] - mn1);
            rs0 += p00 + p01; rs1 += p10 + p11;
            Ps[wm+g  ][j*8+2*tg]   = f2tf(p00);
            Ps[wm+g  ][j*8+2*tg+1] = f2tf(p01);
            Ps[wm+g+8][j*8+2*tg]   = f2tf(p10);
            Ps[wm+g+8][j*8+2*tg+1] = f2tf(p11);
        }
        rs0 += __shfl_xor_sync(~0u, rs0, 1); rs0 += __shfl_xor_sync(~0u, rs0, 2);
        rs1 += __shfl_xor_sync(~0u, rs1, 1); rs1 += __shfl_xor_sync(~0u, rs1, 2);
        l0 = l0*a0 + rs0; l1 = l1*a1 + rs1;
        m0 = mn0; m1 = mn1;
        #pragma unroll
        for (int j = 0; j < 8; j++) {
            o[j][0] *= a0; o[j][1] *= a0; o[j][2] *= a1; o[j][3] *= a1;
        }
        __syncwarp();

        #pragma unroll
        for (int ks = 0; ks < 16; ks++) {
            uint32_t af[4];
            af[0] = Ps[wm+g  ][ks*8+tg];
            af[1] = Ps[wm+g+8][ks*8+tg];
            af[2] = Ps[wm+g  ][ks*8+tg+4];
            af[3] = Ps[wm+g+8][ks*8+tg+4];
            #pragma unroll
            for (int jd = 0; jd < 8; jd++) {
                uint32_t bf[2];
                bf[0] = Vs[ks*8+tg  ][jd*8+g];
                bf[1] = Vs[ks*8+tg+4][jd*8+g];
                mma8(o[jd], af, bf);
            }
        }
    }

    float il0 = 1.0f / l0, il1 = 1.0f / l1;
    int r0 = b*NN + mb + wm + g, r1 = r0 + 8;
    #pragma unroll
    for (int jd = 0; jd < 8; jd++) {
        int c0 = h*64 + jd*8 + 2*tg;
        out[(size_t)r0*CC + c0]     = rnd_tf32(o[jd][0]*il0);
        out[(size_t)r0*CC + c0 + 1] = rnd_tf32(o[jd][1]*il0);
        out[(size_t)r1*CC + c0]     = rnd_tf32(o[jd][2]*il1);
        out[(size_t)r1*CC + c0 + 1] = rnd_tf32(o[jd][3]*il1);
    }
}

// ---------------- tf32 tensor-core GEMM (NT), cp.async 4-stage pipeline ----------
// operands pre-rounded to tf32 in gmem -> HW truncation lossless.
// EP: 0 plain; 1 +bias[n](+addm); 2 gelu(v+bias[n]) rounded to tf32.
#define TG_STG 4
#define TG_STRIDE 20
#define TG_STAGE_F (128 * TG_STRIDE)
#define TG_SMEM (TG_STG * 2 * TG_STAGE_F * 4)     // 81920 bytes
template<int EP>
__global__ __launch_bounds__(256)
void tgemm(const float* __restrict__ A, int lda,
           const float* __restrict__ B, int ldb,
           float* __restrict__ C, int ldc, int K,
           const float* __restrict__ bias, const float* __restrict__ addm)
{
    constexpr int BM = 128, BN = 128, BK = 16;
    extern __shared__ float tsm[];
    auto As = [&](int s) -> float* { return tsm + s * 2 * TG_STAGE_F; };
    auto Bs = [&](int s) -> float* { return tsm + s * 2 * TG_STAGE_F + TG_STAGE_F; };

    int tid = threadIdx.x;
    int warp = tid >> 5, lane = tid & 31;
    int wm = (warp & 1) * 64, wn = (warp >> 1) * 32;
    int g = lane >> 2, tg = lane & 3;
    int bm = blockIdx.y * BM, bn = blockIdx.x * BN;

    float acc[4][4][4];
    #pragma unroll
    for (int i = 0; i < 4; i++)
        #pragma unroll
        for (int j = 0; j < 4; j++)
            #pragma unroll
            for (int q = 0; q < 4; q++) acc[i][j][q] = 0.f;

    int lrow = tid >> 2, lk4 = (tid & 3) * 4;
    const float* Ab = A + (size_t)(bm + lrow) * lda + lk4;
    const float* Bb = B + (size_t)(bn + lrow) * ldb + lk4;
    const float* Ab2 = Ab + (size_t)64 * lda;
    const float* Bb2 = Bb + (size_t)64 * ldb;

    auto issue = [&](int kt, int s) {
        CP16(smem_u32(As(s) + lrow*TG_STRIDE + lk4),        Ab  + kt);
        CP16(smem_u32(As(s) + (lrow+64)*TG_STRIDE + lk4),   Ab2 + kt);
        CP16(smem_u32(Bs(s) + lrow*TG_STRIDE + lk4),        Bb  + kt);
        CP16(smem_u32(Bs(s) + (lrow+64)*TG_STRIDE + lk4),   Bb2 + kt);
        CP_COMMIT();
    };

    int nk = K / BK;
    issue(0, 0);
    if (nk > 1) issue(BK, 1);
    if (nk > 2) issue(2*BK, 2);

    for (int c = 0; c < nk; c++) {
        int rem = nk - 1 - c;
        if (rem >= 2)      asm volatile("cp.async.wait_group 2;" ::: "memory");
        else if (rem == 1) asm volatile("cp.async.wait_group 1;" ::: "memory");
        else               asm volatile("cp.async.wait_group 0;" ::: "memory");
        __syncthreads();
        int s = c & 3;
        const float* as = As(s);
        const float* bs = Bs(s);

        #pragma unroll
        for (int ks = 0; ks < 16; ks += 8) {
            uint32_t af[4][4]; uint32_t bf[4][2];
            #pragma unroll
            for (int i = 0; i < 4; i++) {
                int r = wm + 16*i + g;
                af[i][0] = __float_as_uint(as[r*TG_STRIDE     + ks+tg]);
                af[i][1] = __float_as_uint(as[(r+8)*TG_STRIDE + ks+tg]);
                af[i][2] = __float_as_uint(as[r*TG_STRIDE     + ks+tg+4]);
                af[i][3] = __float_as_uint(as[(r+8)*TG_STRIDE + ks+tg+4]);
            }
            #pragma unroll
            for (int j = 0; j < 4; j++) {
                int n = wn + 8*j + g;
                bf[j][0] = __float_as_uint(bs[n*TG_STRIDE + ks+tg]);
                bf[j][1] = __float_as_uint(bs[n*TG_STRIDE + ks+tg+4]);
            }
            #pragma unroll
            for (int i = 0; i < 4; i++)
                #pragma unroll
                for (int j = 0; j < 4; j++)
                    mma8(acc[i][j], af[i], bf[j]);
        }

        if (c + 3 < nk) issue((c + 3) * BK, (c + 3) & 3);
    }

    #pragma unroll
    for (int i = 0; i < 4; i++) {
        int r0 = bm + wm + 16*i + g;
        int r1 = r0 + 8;
        #pragma unroll
        for (int j = 0; j < 4; j++) {
            int c0 = bn + wn + 8*j + tg*2;
            float v00 = acc[i][j][0], v01 = acc[i][j][1];
            float v10 = acc[i][j][2], v11 = acc[i][j][3];
            if (EP == 1 || EP == 2) {
                float b0 = bias[c0], b1 = bias[c0+1];
                v00 += b0; v01 += b1; v10 += b0; v11 += b1;
            }
            if (EP == 1 && addm) {
                v00 += addm[(size_t)r0*ldc + c0]; v01 += addm[(size_t)r0*ldc + c0 + 1];
                v10 += addm[(size_t)r1*ldc + c0]; v11 += addm[(size_t)r1*ldc + c0 + 1];
            }
            if (EP == 2) {
                v00 = rnd_tf32(0.5f*v00*(1.0f + erff(v00*0.70710678118654752f)));
                v01 = rnd_tf32(0.5f*v01*(1.0f + erff(v01*0.70710678118654752f)));
                v10 = rnd_tf32(0.5f*v10*(1.0f + erff(v10*0.70710678118654752f)));
                v11 = rnd_tf32(0.5f*v11*(1.0f + erff(v11*0.70710678118654752f)));
            }
            C[(size_t)r0*ldc + c0]     = v00;
            C[(size_t)r0*ldc + c0 + 1] = v01;
            C[(size_t)r1*ldc + c0]     = v10;
            C[(size_t)r1*ldc + c0 + 1] = v11;
        }
    }
}

// ---------------- launch ----------------
extern "C" void kernel_launch(void* const* d_in, const int* in_sizes, int n_in,
                              void* d_out, int out_size) {
    const float* x      = (const float*)d_in[0];
    const float* ln1_w  = (const float*)d_in[1];
    const float* ln1_b  = (const float*)d_in[2];
    const float* qkv_w  = (const float*)d_in[3];
    const float* out_w  = (const float*)d_in[4];
    const float* out_b  = (const float*)d_in[5];
    const float* conv_w = (const float*)d_in[6];
    const float* conv_b = (const float*)d_in[7];
    const float* ln2_w  = (const float*)d_in[8];
    const float* ln2_b  = (const float*)d_in[9];
    const float* ff1_w  = (const float*)d_in[10];
    const float* ff1_b  = (const float*)d_in[11];
    const float* ff2_w  = (const float*)d_in[12];
    const float* ff2_b  = (const float*)d_in[13];
    float* out = (float*)d_out;

    float *xn, *xnr, *qkv, *part, *wv, *scores, *mask, *attn, *conv, *xr, *hbuf, *ff, *wr;
    cudaGetSymbolAddress((void**)&xn,     g_xn);
    cudaGetSymbolAddress((void**)&xnr,    g_xnr);
    cudaGetSymbolAddress((void**)&qkv,    g_qkv);
    cudaGetSymbolAddress((void**)&part,   g_part);
    cudaGetSymbolAddress((void**)&wv,     g_w);
    cudaGetSymbolAddress((void**)&scores, g_scores);
    cudaGetSymbolAddress((void**)&mask,   g_mask);
    cudaGetSymbolAddress((void**)&attn,   g_attn);
    cudaGetSymbolAddress((void**)&conv,   g_conv);
    cudaGetSymbolAddress((void**)&xr,     g_xr);
    cudaGetSymbolAddress((void**)&hbuf,   g_h);
    cudaGetSymbolAddress((void**)&ff,     g_ff);
    cudaGetSymbolAddress((void**)&wr,     g_wr);

    // idempotent every call (capture-safe, no static guards)
    const int FA_SMEM = (3*128*QK_PAD + 128*P_PAD) * 4;   // 172032 B
    cudaFuncSetAttribute(flash_attn, cudaFuncAttributeMaxDynamicSharedMemorySize, FA_SMEM);
    cudaFuncSetAttribute(tgemm<0>, cudaFuncAttributeMaxDynamicSharedMemorySize, TG_SMEM);
    cudaFuncSetAttribute(tgemm<1>, cudaFuncAttributeMaxDynamicSharedMemorySize, TG_SMEM);
    cudaFuncSetAttribute(tgemm<2>, cudaFuncAttributeMaxDynamicSharedMemorySize, TG_SMEM);

    // parallel graph branches via stream fork/join off the capturing (legacy) stream
    cudaStream_t sA, sB, sC;
    cudaStreamCreateWithFlags(&sA, cudaStreamNonBlocking);
    cudaStreamCreateWithFlags(&sB, cudaStreamNonBlocking);
    cudaStreamCreateWithFlags(&sC, cudaStreamNonBlocking);
    cudaEvent_t eRoot, eWq, eWall, eLN1, eMask, eConv;
    cudaEventCreateWithFlags(&eRoot, cudaEventDisableTiming);
    cudaEventCreateWithFlags(&eWq,   cudaEventDisableTiming);
    cudaEventCreateWithFlags(&eWall, cudaEventDisableTiming);
    cudaEventCreateWithFlags(&eLN1,  cudaEventDisableTiming);
    cudaEventCreateWithFlags(&eMask, cudaEventDisableTiming);
    cudaEventCreateWithFlags(&eConv, cudaEventDisableTiming);

    cudaEventRecord(eRoot, 0);
    cudaStreamWaitEvent(sA, eRoot, 0);
    cudaStreamWaitEvent(sC, eRoot, 0);

    // branch A: weight rounding
    round_tf32<<<768,  256, 0, sA>>>((const float4*)qkv_w, (float4*)(wr + WR_QW), 786432/4);
    cudaEventRecord(eWq, sA);
    round_tf32<<<256,  256, 0, sA>>>((const float4*)out_w, (float4*)(wr + WR_OW), 262144/4);
    round_tf32<<<1024, 256, 0, sA>>>((const float4*)ff1_w, (float4*)(wr + WR_F1), 1048576/4);
    round_tf32<<<1024, 256, 0, sA>>>((const float4*)ff2_w, (float4*)(wr + WR_F2), 1048576/4);
    cudaEventRecord(eWall, sA);

    // branch C: conv (depends only on x)
    dwconv<<<M_TOK, CC, 0, sC>>>(x, conv_w, conv_b, conv);
    cudaEventRecord(eConv, sC);

    // main: LN1 (exact xn + rounded xnr)
    ln_kernel<2><<<M_TOK, 256>>>(x, ln1_w, ln1_b, xn, xnr);
    cudaEventRecord(eLN1, 0);
    cudaStreamWaitEvent(sB, eLN1, 0);

    // branch B: exact fp32 mask path
    xn_part<<<dim3(8, 8), 512, 0, sB>>>(xn, part);
    wvec<<<HEADS, 512, 0, sB>>>(part, qkv_w, wv);
    head_scores3<<<dim3(8, 128), 256, 0, sB>>>(xn, wv, scores);
    topk_mask<<<2*HEADS, 1024, 0, sB>>>(scores, mask);
    cudaEventRecord(eMask, sB);

    // main: QKV GEMM (needs rounded qkv_w)
    cudaStreamWaitEvent(0, eWq, 0);
    tgemm<0><<<dim3(12, 64), 256, TG_SMEM>>>(xnr, CC, wr + WR_QW, CC, qkv, 3*CC, CC, nullptr, nullptr);

    // main: fused attention (needs masks)
    cudaStreamWaitEvent(0, eMask, 0);
    flash_attn<<<dim3(8, HEADS), 256, FA_SMEM>>>(qkv, mask, attn);

    // main: out-proj + bias + conv -> xr (needs conv and remaining weights)
    cudaStreamWaitEvent(0, eConv, 0);
    cudaStreamWaitEvent(0, eWall, 0);
    tgemm<1><<<dim3(4, 64), 256, TG_SMEM>>>(attn, CC, wr + WR_OW, CC, xr, CC, CC, out_b, conv);

    // main: LN2 -> rounded hbuf
    ln_kernel<1><<<M_TOK, 256>>>(xr, ln2_w, ln2_b, hbuf, nullptr);

    // main: FF1 + gelu (rounded output)
    tgemm<2><<<dim3(16, 64), 256, TG_SMEM>>>(hbuf, CC, wr + WR_F1, CC, ff, FF, CC, ff1_b, nullptr);

    // main: FF2 + bias + residual -> out
    tgemm<1><<<dim3(4, 64), 256, TG_SMEM>>>(ff, FF, wr + WR_F2, FF, out, CC, FF, ff2_b, xr);

    cudaEventDestroy(eRoot); cudaEventDestroy(eWq); cudaEventDestroy(eWall);
    cudaEventDestroy(eLN1);  cudaEventDestroy(eMask); cudaEventDestroy(eConv);
    cudaStreamDestroy(sA); cudaStreamDestroy(sB); cudaStreamDestroy(sC);
}